// round 13
// baseline (speedup 1.0000x reference)
#include <cuda_runtime.h>
#include <cuda_fp16.h>
#include <math.h>

// ---------------- problem constants ----------------
#define NMAX 50048            // N = 50000 nodes (padded)
#define EMAX 1600512
#define FIN  512
#define D1   64               // H1*hid = 8*8
#define H1N  8
#define D2   40               // C (H2=1)
#define SCB  196              // scan blocks: 196*256 = 50176 >= 50000

// ---------------- scratch (device globals; no allocation allowed) ----------------
__device__ __align__(16) float  g_h1 [NMAX * D1];   // x @ W1 (fp32)
__device__ __align__(16) __half g_h1h[NMAX * D1];   // fp16 shadow (gathers)
__device__ __align__(16) float  g_as1[NMAX * H1N];
__device__ __align__(16) float  g_ad1[NMAX * H1N];
__device__ __align__(16) float  g_z1 [NMAX * D1];   // relu(agg + b1): GEMM2 input
__device__ __align__(16) float  g_h2 [NMAX * D2];
__device__ __align__(16) __half g_h2h[NMAX * D2];   // fp16 shadow (gathers)
__device__ __align__(16) float  g_as2[NMAX];
__device__ __align__(16) float  g_ad2[NMAX];
// CSR-by-dst (built once per launch, shared by both layers)
__device__ int g_cnt[NMAX];
__device__ int g_row[NMAX + 1];
__device__ int g_cur[NMAX];
__device__ int g_part[SCB + 1];
__device__ int g_srt[EMAX];      // src ids, grouped by dst

__device__ __forceinline__ unsigned tf32_of(float x) {
    unsigned r;
    asm("cvt.rna.tf32.f32 %0, %1;" : "=r"(r) : "f"(x));
    return r;
}
__device__ __forceinline__ float lrelu(float v) { return (v >= 0.f) ? v : 0.2f * v; }

// ---------------- CSR build ------------------------------------------------------
__global__ void k_zero(int Nn) {
    int i = blockIdx.x * blockDim.x + threadIdx.x;
    if (i < NMAX) g_cnt[i] = 0;
}
__global__ void k_hist(const int* __restrict__ ei, int E) {
    int i4 = (blockIdx.x * blockDim.x + threadIdx.x) * 4;
    if (i4 + 3 < E) {
        int4 d = *(const int4*)(ei + E + i4);
        atomicAdd(&g_cnt[d.x], 1);
        atomicAdd(&g_cnt[d.y], 1);
        atomicAdd(&g_cnt[d.z], 1);
        atomicAdd(&g_cnt[d.w], 1);
    } else {
        for (int k = i4; k < E; k++) atomicAdd(&g_cnt[__ldg(ei + E + k)], 1);
    }
}
__global__ void k_scan1() {
    __shared__ int sh[256];
    int t = threadIdx.x, b = blockIdx.x;
    int i = b * 256 + t;
    int v = (i < NMAX) ? g_cnt[i] : 0;
    sh[t] = v;
    __syncthreads();
#pragma unroll
    for (int off = 128; off; off >>= 1) {
        if (t < off) sh[t] += sh[t + off];
        __syncthreads();
    }
    if (t == 0) g_part[b] = sh[0];
}
__global__ void k_scan2() {
    __shared__ int sh[SCB];
    int t = threadIdx.x;
    int v = (t < SCB) ? g_part[t] : 0;
    if (t < SCB) sh[t] = v;
    __syncthreads();
    for (int off = 1; off < SCB; off <<= 1) {
        int u = 0;
        if (t < SCB && t >= off) u = sh[t - off];
        __syncthreads();
        if (t < SCB) sh[t] += u;
        __syncthreads();
    }
    if (t < SCB) g_part[t] = sh[t] - v;   // exclusive
    if (t == SCB - 1) g_part[SCB] = sh[SCB - 1];
}
__global__ void k_scan3(int Nn) {
    __shared__ int sh[256];
    int t = threadIdx.x, b = blockIdx.x;
    int i = b * 256 + t;
    int v = (i < NMAX) ? g_cnt[i] : 0;
    sh[t] = v;
    __syncthreads();
    for (int off = 1; off < 256; off <<= 1) {
        int u = (t >= off) ? sh[t - off] : 0;
        __syncthreads();
        sh[t] += u;
        __syncthreads();
    }
    int excl = sh[t] - v + g_part[b];
    if (i <= Nn) {
        g_row[i] = excl;
        if (i < Nn) g_cur[i] = excl;
    }
}
__global__ void k_scatter(const int* __restrict__ ei, int E) {
    int i = blockIdx.x * blockDim.x + threadIdx.x;
    if (i >= E) return;
    int s = __ldg(ei + i), d = __ldg(ei + E + i);
    int p = atomicAdd(&g_cur[d], 1);
    g_srt[p] = s;
}

// ---------------- GEMM1 (tf32 MMA): h1 = x @ W1   (M x 512) @ (512 x 64) -------
__global__ void k_gemm1(const float* __restrict__ A, const float* __restrict__ B, int M) {
    __shared__ __align__(16) float As[128 * 36];
    __shared__ __align__(16) float Bs[64 * 36];
    const int tid  = threadIdx.x;
    const int warp = tid >> 5, lane = tid & 31;
    const int row0 = blockIdx.x * 128;
    const int lr = lane >> 2, lc = lane & 3;

    float acc[8][4];
#pragma unroll
    for (int nt = 0; nt < 8; nt++)
#pragma unroll
        for (int j = 0; j < 4; j++) acc[nt][j] = 0.f;

    for (int k0 = 0; k0 < FIN; k0 += 32) {
#pragma unroll
        for (int i = 0; i < 4; i++) {
            int idx = tid + i * 256;
            int r = idx >> 3, c4 = idx & 7;
            float4 v = make_float4(0.f, 0.f, 0.f, 0.f);
            int gr = row0 + r;
            if (gr < M) v = *(const float4*)(A + (size_t)gr * FIN + k0 + c4 * 4);
            int c = c4 * 4;
            As[r * 36 + ((c + 0) & 7) * 4 + ((c + 0) >> 3)] = __uint_as_float(tf32_of(v.x));
            As[r * 36 + ((c + 1) & 7) * 4 + ((c + 1) >> 3)] = __uint_as_float(tf32_of(v.y));
            As[r * 36 + ((c + 2) & 7) * 4 + ((c + 2) >> 3)] = __uint_as_float(tf32_of(v.z));
            As[r * 36 + ((c + 3) & 7) * 4 + ((c + 3) >> 3)] = __uint_as_float(tf32_of(v.w));
        }
#pragma unroll
        for (int i = 0; i < 2; i++) {
            int idx = tid + i * 256;
            int k = idx >> 4, c4 = idx & 15;
            float4 v = *(const float4*)(B + (size_t)(k0 + k) * D1 + c4 * 4);
            int kk = ((k & 7) << 2) + (k >> 3);
            Bs[(c4 * 4 + 0) * 36 + kk] = __uint_as_float(tf32_of(v.x));
            Bs[(c4 * 4 + 1) * 36 + kk] = __uint_as_float(tf32_of(v.y));
            Bs[(c4 * 4 + 2) * 36 + kk] = __uint_as_float(tf32_of(v.z));
            Bs[(c4 * 4 + 3) * 36 + kk] = __uint_as_float(tf32_of(v.w));
        }
        __syncthreads();

        const float* ab = As + (warp * 16 + lr) * 36;
        float4 a00 = *(const float4*)(ab +        lc * 4);
        float4 a10 = *(const float4*)(ab + 8*36 + lc * 4);
        float4 a01 = *(const float4*)(ab +        (lc + 4) * 4);
        float4 a11 = *(const float4*)(ab + 8*36 + (lc + 4) * 4);
        const unsigned* a00u = (const unsigned*)&a00;
        const unsigned* a10u = (const unsigned*)&a10;
        const unsigned* a01u = (const unsigned*)&a01;
        const unsigned* a11u = (const unsigned*)&a11;

#pragma unroll
        for (int nt = 0; nt < 8; nt++) {
            const float* bb = Bs + (nt * 8 + lr) * 36;
            float4 b0v = *(const float4*)(bb + lc * 4);
            float4 b1v = *(const float4*)(bb + (lc + 4) * 4);
            const unsigned* b0u = (const unsigned*)&b0v;
            const unsigned* b1u = (const unsigned*)&b1v;
#pragma unroll
            for (int ks = 0; ks < 4; ks++) {
                asm volatile(
                    "mma.sync.aligned.m16n8k8.row.col.f32.tf32.tf32.f32 "
                    "{%0,%1,%2,%3}, {%4,%5,%6,%7}, {%8,%9}, {%0,%1,%2,%3};"
                    : "+f"(acc[nt][0]), "+f"(acc[nt][1]), "+f"(acc[nt][2]), "+f"(acc[nt][3])
                    : "r"(a00u[ks]), "r"(a10u[ks]), "r"(a01u[ks]), "r"(a11u[ks]),
                      "r"(b0u[ks]), "r"(b1u[ks]));
            }
        }
        __syncthreads();
    }

    int gr = row0 + warp * 16 + lr;
#pragma unroll
    for (int nt = 0; nt < 8; nt++) {
        int col = nt * 8 + lc * 2;
        if (gr < M)     *(float2*)(g_h1 + (size_t)gr * D1 + col)       = make_float2(acc[nt][0], acc[nt][1]);
        if (gr + 8 < M) *(float2*)(g_h1 + (size_t)(gr + 8) * D1 + col) = make_float2(acc[nt][2], acc[nt][3]);
    }
}

// ---------------- att1 + fp16 shadow: thread = (node, head) ---------------------
__global__ void k_att1(const float* __restrict__ asrc, const float* __restrict__ adst, int Nn) {
    int idx = blockIdx.x * blockDim.x + threadIdx.x;
    if (idx >= Nn * H1N) return;
    int n = idx >> 3, h = idx & 7;
    const float* hp = g_h1 + (size_t)n * D1 + h * 8;
    float s = 0.f, d = 0.f;
    __half hb[8];
#pragma unroll
    for (int c = 0; c < 8; c++) {
        float v = hp[c];
        s += v * __ldg(asrc + h * 8 + c);
        d += v * __ldg(adst + h * 8 + c);
        hb[c] = __float2half_rn(v);
    }
    *(uint4*)(g_h1h + (size_t)n * D1 + h * 8) = *(uint4*)hb;
    g_as1[idx] = s;
    g_ad1[idx] = d;
}

// ---------------- layer-1 aggregate: QUARTER-WARP per node, fp16 gathers --------
// quarter q owns node w*4+q; lane ll (0..7) owns head ll = features 8ll..8ll+7.
// Per-lane attention + per-lane denominator: zero shuffles.
__global__ void k_agg1(const float* __restrict__ b1, int Nn) {
    int w = (blockIdx.x * blockDim.x + threadIdx.x) >> 5;
    int lane = threadIdx.x & 31;
    if (w * 4 >= Nn) return;              // uniform whole-warp exit
    int q = lane >> 3;
    int ll = lane & 7;                    // head index
    int n = w * 4 + q;
    bool valid = (n < Nn);
    int nc = valid ? n : (Nn - 1);        // clamp

    float adh = g_ad1[nc * H1N + ll];

    // self-loop: fp32 own row (exact)
    float ex = __expf(lrelu(g_as1[nc * H1N + ll] + adh));
    const float4* hp = (const float4*)(g_h1 + (size_t)nc * D1 + ll * 8);
    float4 p0 = hp[0], p1 = hp[1];
    float a0 = ex * p0.x, a1 = ex * p0.y, a2 = ex * p0.z, a3 = ex * p0.w;
    float a4 = ex * p1.x, a5 = ex * p1.y, a6 = ex * p1.z, a7 = ex * p1.w;
    float den = ex;

    int j = g_row[nc], end = g_row[nc + 1];
    for (; j + 2 <= end; j += 2) {
        int s0 = __ldg(g_srt + j), s1 = __ldg(g_srt + j + 1);
        float e0 = __ldg(g_as1 + s0 * H1N + ll) + adh;
        float e1 = __ldg(g_as1 + s1 * H1N + ll) + adh;
        uint4 r0 = __ldg((const uint4*)(g_h1h + (size_t)s0 * D1 + ll * 8));
        uint4 r1 = __ldg((const uint4*)(g_h1h + (size_t)s1 * D1 + ll * 8));
        float x0 = __expf(lrelu(e0)), x1 = __expf(lrelu(e1));
        const __half2* h0 = (const __half2*)&r0;
        const __half2* h1 = (const __half2*)&r1;
        float2 c00 = __half22float2(h0[0]), c01 = __half22float2(h0[1]);
        float2 c02 = __half22float2(h0[2]), c03 = __half22float2(h0[3]);
        float2 c10 = __half22float2(h1[0]), c11 = __half22float2(h1[1]);
        float2 c12 = __half22float2(h1[2]), c13 = __half22float2(h1[3]);
        a0 += x0 * c00.x + x1 * c10.x;  a1 += x0 * c00.y + x1 * c10.y;
        a2 += x0 * c01.x + x1 * c11.x;  a3 += x0 * c01.y + x1 * c11.y;
        a4 += x0 * c02.x + x1 * c12.x;  a5 += x0 * c02.y + x1 * c12.y;
        a6 += x0 * c03.x + x1 * c13.x;  a7 += x0 * c03.y + x1 * c13.y;
        den += x0 + x1;
    }
    if (j < end) {
        int s0 = __ldg(g_srt + j);
        float x0 = __expf(lrelu(__ldg(g_as1 + s0 * H1N + ll) + adh));
        uint4 r0 = __ldg((const uint4*)(g_h1h + (size_t)s0 * D1 + ll * 8));
        const __half2* h0 = (const __half2*)&r0;
        float2 c00 = __half22float2(h0[0]), c01 = __half22float2(h0[1]);
        float2 c02 = __half22float2(h0[2]), c03 = __half22float2(h0[3]);
        a0 += x0 * c00.x;  a1 += x0 * c00.y;
        a2 += x0 * c01.x;  a3 += x0 * c01.y;
        a4 += x0 * c02.x;  a5 += x0 * c02.y;
        a6 += x0 * c03.x;  a7 += x0 * c03.y;
        den += x0;
    }

    if (valid) {
        float inv = 1.f / (den + 1e-16f);
        float4 bv0 = *(const float4*)(b1 + ll * 8);
        float4 bv1 = *(const float4*)(b1 + ll * 8 + 4);
        float4 z0, z1;
        z0.x = fmaxf(a0 * inv + bv0.x, 0.f);
        z0.y = fmaxf(a1 * inv + bv0.y, 0.f);
        z0.z = fmaxf(a2 * inv + bv0.z, 0.f);
        z0.w = fmaxf(a3 * inv + bv0.w, 0.f);
        z1.x = fmaxf(a4 * inv + bv1.x, 0.f);
        z1.y = fmaxf(a5 * inv + bv1.y, 0.f);
        z1.z = fmaxf(a6 * inv + bv1.z, 0.f);
        z1.w = fmaxf(a7 * inv + bv1.w, 0.f);
        float4* zp = (float4*)(g_z1 + (size_t)n * D1 + ll * 8);
        zp[0] = z0;
        zp[1] = z1;
    }
}

// ---------------- GEMM2: h2 = z1 @ W2  (M x 64) @ (64 x 40) --------------------
__global__ void k_gemm2(const float* __restrict__ W2, int M) {
    __shared__ __align__(16) float As[64][65];
    __shared__ __align__(16) float Bs[64][D2];
    const int tid = threadIdx.x;
    const int row0 = blockIdx.x * 64;

    for (int idx = tid; idx < 64 * D2; idx += 256)
        Bs[idx / D2][idx % D2] = W2[idx];

#pragma unroll
    for (int i = 0; i < 4; i++) {
        int idx = tid + i * 256;
        int r = idx >> 4, c = idx & 15;
        int gr = row0 + r;
        float4 v = make_float4(0.f, 0.f, 0.f, 0.f);
        if (gr < M) v = *(const float4*)(g_z1 + (size_t)gr * D1 + c * 4);
        As[r][c * 4 + 0] = v.x; As[r][c * 4 + 1] = v.y;
        As[r][c * 4 + 2] = v.z; As[r][c * 4 + 3] = v.w;
    }
    __syncthreads();

    int row = tid & 63;
    int cg  = tid >> 6;
    float acc[10];
#pragma unroll
    for (int j = 0; j < 10; j++) acc[j] = 0.f;
#pragma unroll
    for (int k = 0; k < 64; k++) {
        float a = As[row][k];
#pragma unroll
        for (int j = 0; j < 10; j++) acc[j] += a * Bs[k][cg * 10 + j];
    }
    int gr = row0 + row;
    if (gr < M) {
#pragma unroll
        for (int j = 0; j < 10; j++)
            g_h2[(size_t)gr * D2 + cg * 10 + j] = acc[j];
    }
}

// ---------------- att2 + fp16 shadow: thread per node ---------------------------
__global__ void k_att2(const float* __restrict__ s2, const float* __restrict__ d2, int Nn) {
    int n = blockIdx.x * blockDim.x + threadIdx.x;
    if (n >= Nn) return;
    const float* hp = g_h2 + (size_t)n * D2;
    float s = 0.f, d = 0.f;
    __half hb[D2];
#pragma unroll
    for (int j = 0; j < D2; j++) {
        float v = hp[j];
        s += v * __ldg(s2 + j);
        d += v * __ldg(d2 + j);
        hb[j] = __float2half_rn(v);
    }
    uint4* dst = (uint4*)(g_h2h + (size_t)n * D2);   // 80B row, 16B aligned
#pragma unroll
    for (int j = 0; j < 5; j++) dst[j] = ((uint4*)hb)[j];
    g_as2[n] = s;
    g_ad2[n] = d;
}

// ---------------- layer-2 aggregate + log_softmax: HALF-WARP, fp16 gathers -----
// half owns a node; lanes ll<10 carry features 4ll..4ll+3 (half4 = 8B loads).
__global__ void k_agg2(const float* __restrict__ b2, float* __restrict__ out, int Nn) {
    int w = (blockIdx.x * blockDim.x + threadIdx.x) >> 5;
    int lane = threadIdx.x & 31;
    if (w * 2 >= Nn) return;              // uniform whole-warp exit
    int half = lane >> 4;
    int ll = lane & 15;
    bool act = (ll < 10);
    int lv = act ? ll : 0;                // clamped feature lane
    int n = w * 2 + half;
    bool valid = (n < Nn);
    int nc = valid ? n : (Nn - 1);

    float adn = g_ad2[nc];

    // self-loop: fp32 own row
    float ex = __expf(lrelu(g_as2[nc] + adn));
    float4 hv = *(const float4*)(g_h2 + (size_t)nc * D2 + lv * 4);
    float ax = 0.f, ay = 0.f, az = 0.f, aw = 0.f;
    if (act) { ax = ex * hv.x; ay = ex * hv.y; az = ex * hv.z; aw = ex * hv.w; }
    float den = ex;                       // replicated per lane

    int j = g_row[nc], end = g_row[nc + 1];
    for (; j + 2 <= end; j += 2) {
        int s0 = __ldg(g_srt + j), s1 = __ldg(g_srt + j + 1);
        float x0 = __expf(lrelu(__ldg(g_as2 + s0) + adn));
        float x1 = __expf(lrelu(__ldg(g_as2 + s1) + adn));
        uint2 r0 = __ldg((const uint2*)(g_h2h + (size_t)s0 * D2 + lv * 4));
        uint2 r1 = __ldg((const uint2*)(g_h2h + (size_t)s1 * D2 + lv * 4));
        if (act) {
            float2 c00 = __half22float2(*(__half2*)&r0.x);
            float2 c01 = __half22float2(*(__half2*)&r0.y);
            float2 c10 = __half22float2(*(__half2*)&r1.x);
            float2 c11 = __half22float2(*(__half2*)&r1.y);
            ax += x0 * c00.x + x1 * c10.x;
            ay += x0 * c00.y + x1 * c10.y;
            az += x0 * c01.x + x1 * c11.x;
            aw += x0 * c01.y + x1 * c11.y;
        }
        den += x0 + x1;
    }
    if (j < end) {
        int s0 = __ldg(g_srt + j);
        float x0 = __expf(lrelu(__ldg(g_as2 + s0) + adn));
        uint2 r0 = __ldg((const uint2*)(g_h2h + (size_t)s0 * D2 + lv * 4));
        if (act) {
            float2 c00 = __half22float2(*(__half2*)&r0.x);
            float2 c01 = __half22float2(*(__half2*)&r0.y);
            ax += x0 * c00.x; ay += x0 * c00.y; az += x0 * c01.x; aw += x0 * c01.y;
        }
        den += x0;
    }

    __syncwarp();
    float inv = 1.f / (den + 1e-16f);
    float4 bv = *(const float4*)(b2 + lv * 4);
    float vx = -3.4e38f, vy = -3.4e38f, vz = -3.4e38f, vw = -3.4e38f;
    if (act) {
        vx = ax * inv + bv.x;
        vy = ay * inv + bv.y;
        vz = az * inv + bv.z;
        vw = aw * inv + bv.w;
    }
    // 16-lane max reduce (xor offsets < 16 stay within the half)
    float m = fmaxf(fmaxf(vx, vy), fmaxf(vz, vw));
#pragma unroll
    for (int off = 8; off; off >>= 1) m = fmaxf(m, __shfl_xor_sync(0xffffffffu, m, off));
    float s = act ? (__expf(vx - m) + __expf(vy - m) + __expf(vz - m) + __expf(vw - m)) : 0.f;
#pragma unroll
    for (int off = 8; off; off >>= 1) s += __shfl_xor_sync(0xffffffffu, s, off);
    float l = m + logf(s);
    if (valid && act) {
        float4 o = make_float4(vx - l, vy - l, vz - l, vw - l);
        *(float4*)(out + (size_t)n * D2 + ll * 4) = o;
    }
}

// ---------------- launch: fork CSR build || GEMM1+att1, join at agg1 ------------
extern "C" void kernel_launch(void* const* d_in, const int* in_sizes, int n_in,
                              void* d_out, int out_size) {
    const float* x   = (const float*)d_in[0];
    const int*   ei  = (const int*)d_in[1];       // int32 (JAX x64 disabled)
    const float* W1  = (const float*)d_in[2];
    const float* as1 = (const float*)d_in[3];
    const float* ad1 = (const float*)d_in[4];
    const float* b1  = (const float*)d_in[5];
    const float* W2  = (const float*)d_in[6];
    const float* as2 = (const float*)d_in[7];
    const float* ad2 = (const float*)d_in[8];
    const float* b2  = (const float*)d_in[9];

    int Nn = in_sizes[0] / FIN;      // 50000
    int E  = in_sizes[1] / 2;        // 1600000
    int nw1 = (Nn + 3) / 4;          // agg1: 4 nodes per warp
    int nb1 = (nw1 * 32 + 255) / 256;
    int nw2 = (Nn + 1) / 2;          // agg2: 2 nodes per warp
    int nb2 = (nw2 * 32 + 255) / 256;

    // Side stream + events, created per call. NOT destroyed: destroying a
    // stream/event participating in an active capture invalidates the capture.
    cudaStream_t s2;
    cudaStreamCreateWithFlags(&s2, cudaStreamNonBlocking);
    cudaEvent_t eFork, eJoin;
    cudaEventCreateWithFlags(&eFork, cudaEventDisableTiming);
    cudaEventCreateWithFlags(&eJoin, cudaEventDisableTiming);

    // fork: s2 inherits capture dependency from the default stream
    cudaEventRecord(eFork, 0);
    cudaStreamWaitEvent(s2, eFork, 0);

    // branch B (side stream): CSR build
    k_zero   <<<(NMAX + 255) / 256, 256, 0, s2>>>(Nn);
    k_hist   <<<(E / 4 + 255) / 256, 256, 0, s2>>>(ei, E);
    k_scan1  <<<SCB, 256, 0, s2>>>();
    k_scan2  <<<1, 256, 0, s2>>>();
    k_scan3  <<<SCB, 256, 0, s2>>>(Nn);
    k_scatter<<<(E + 255) / 256, 256, 0, s2>>>(ei, E);

    // branch A (default stream): dense chain
    k_gemm1  <<<(Nn + 127) / 128, 256>>>(x, W1, Nn);
    k_att1   <<<(Nn * H1N + 255) / 256, 256>>>(as1, ad1, Nn);

    // join: default stream waits for CSR build
    cudaEventRecord(eJoin, s2);
    cudaStreamWaitEvent(0, eJoin, 0);

    k_agg1   <<<nb1, 256>>>(b1, Nn);
    k_gemm2  <<<(Nn + 63) / 64, 256>>>(W2, Nn);
    k_att2   <<<(Nn + 255) / 256, 256>>>(as2, ad2, Nn);
    k_agg2   <<<nb2, 256>>>(b2, (float*)d_out, Nn);
}